// round 12
// baseline (speedup 1.0000x reference)
#include <cuda_runtime.h>
#include <math.h>

#define Bb 16
#define Nn 64
#define Cc 80
#define Hh 128
#define Ww 128
#define HW (Hh*Ww)
#define NB (Bb*Nn)
#define RMAX 16
#define EPS32 1.1920929e-07f
#define TOTAL (Bb*Cc*HW)

#define BG_BLOCKS 2560
#define N4 (TOTAL/4)              // 5,242,880 float4
#define BLK4 (N4/BG_BLOCKS)       // 2048 float4 per bg block = 8 * 256

// Persistent scratch. Invariants between launches (restored every launch):
//   g_ct, g_win all zero; g_acc_*, g_af, g_done zero.
// Zero at module load; phase2 restores g_ct via atomicExch, g_win via CAS,
// and the finalize block rezeros the scalar accumulators.
__device__ int   g_cxi[NB], g_cyi[NB], g_rw[NB], g_cls[NB];
__device__ float g_sig2[NB], g_fx[NB], g_fy[NB], g_sw[NB], g_sh[NB];
__device__ int   g_win[Bb*HW];
__device__ float g_ct[TOTAL];
__device__ double g_acc_bg;      // sum of lg2(1-p)*p^2 (scale by -ln2 at end)
__device__ double g_acc_c;       // focal corrections at ct>0 pixels
__device__ double g_acc_wh, g_acc_of;
__device__ int   g_af;
__device__ int   g_done;

// ---------------------------------------------------------------------------
__device__ __forceinline__ float block_reduce(float v) {
    __shared__ float sh[32];
    int lane = threadIdx.x & 31;
    int wid  = threadIdx.x >> 5;
    #pragma unroll
    for (int o = 16; o > 0; o >>= 1) v += __shfl_down_sync(0xffffffffu, v, o);
    if (lane == 0) sh[wid] = v;
    __syncthreads();
    int nw = (blockDim.x + 31) >> 5;
    v = (threadIdx.x < nw) ? sh[threadIdx.x] : 0.0f;
    if (wid == 0) {
        #pragma unroll
        for (int o = 16; o > 0; o >>= 1) v += __shfl_down_sync(0xffffffffu, v, o);
    }
    return v;  // valid on thread 0
}

__device__ __forceinline__ float f_bg_precise(float p) {
    return -__logf(1.0f - p + 1e-12f) * (p * p);
}

// packed f32x2 helpers
#define PACK2(out, lo, hi) asm("mov.b64 %0, {%1, %2};" : "=l"(out) : "f"(lo), "f"(hi))
#define UNPACK2(lo, hi, in) asm("mov.b64 {%0, %1}, %2;" : "=f"(lo), "=f"(hi) : "l"(in))
#define FMA2(out, a, b, c) asm("fma.rn.f32x2 %0, %1, %2, %3;" : "=l"(out) : "l"(a), "l"(b), "l"(c))
#define MUL2(out, a, b)    asm("mul.rn.f32x2 %0, %1, %2;" : "=l"(out) : "l"(a), "l"(b))
#define LG2(out, in)       asm("lg2.approx.f32 %0, %1;" : "=f"(out) : "f"(in))

// acc += lg2(1-p) * p^2   (elementwise on a packed pair)
__device__ __forceinline__ void bg_pair(unsigned long long P,
                                        unsigned long long NEG2,
                                        unsigned long long ONE2,
                                        unsigned long long& ACC) {
    unsigned long long T, Q, L;
    FMA2(T, P, NEG2, ONE2);         // t = 1 - p
    float t0, t1, l0, l1;
    UNPACK2(t0, t1, T);
    LG2(l0, t0);
    LG2(l1, t1);
    PACK2(L, l0, l1);
    MUL2(Q, P, P);                  // p^2
    FMA2(ACC, L, Q, ACC);           // acc += lg2(t) * p^2
}

__device__ __forceinline__ void bg_quad(float4 v,
                                        unsigned long long NEG2,
                                        unsigned long long ONE2,
                                        unsigned long long& A0,
                                        unsigned long long& A1) {
    unsigned long long P;
    PACK2(P, v.x, v.y); bg_pair(P, NEG2, ONE2, A0);
    PACK2(P, v.z, v.w); bg_pair(P, NEG2, ONE2, A1);
}

// ---------------------------------------------------------------------------
// Phase 1: blocks [0, BG_BLOCKS)   -> dense background lg2-sum over 84 MB
//                                     (8 float4 issued up front; the
//                                     launch_bounds(256,2) register budget
//                                     lets ptxas keep them ALL in flight)
//          blocks [BG_BLOCKS,+NB)  -> per-box params + winner map + gaussian
//                                     scatter-max (fills the bg drain)
__global__ void __launch_bounds__(256, 2) k_phase1(const float4* __restrict__ cp4,
                                                   const float*  __restrict__ boxes,
                                                   const int*    __restrict__ labels) {
    int bid = blockIdx.x;
    if (bid < BG_BLOCKS) {
        // ---- dense background term ----
        const float4* p = cp4 + (size_t)bid * BLK4 + threadIdx.x;
        unsigned long long ONE2, NEG2, A0 = 0, A1 = 0, A2 = 0, A3 = 0;
        PACK2(ONE2, 1.0f, 1.0f);
        PACK2(NEG2, -1.0f, -1.0f);
        // all 8 loads issued up front (MLP=8)
        float4 v0 = p[   0];
        float4 v1 = p[ 256];
        float4 v2 = p[ 512];
        float4 v3 = p[ 768];
        float4 v4 = p[1024];
        float4 v5 = p[1280];
        float4 v6 = p[1536];
        float4 v7 = p[1792];
        bg_quad(v0, NEG2, ONE2, A0, A1);
        bg_quad(v1, NEG2, ONE2, A2, A3);
        bg_quad(v2, NEG2, ONE2, A0, A1);
        bg_quad(v3, NEG2, ONE2, A2, A3);
        bg_quad(v4, NEG2, ONE2, A0, A1);
        bg_quad(v5, NEG2, ONE2, A2, A3);
        bg_quad(v6, NEG2, ONE2, A0, A1);
        bg_quad(v7, NEG2, ONE2, A2, A3);
        float a0, a1, b0, b1, c0, c1, d0, d1;
        UNPACK2(a0, a1, A0); UNPACK2(b0, b1, A1);
        UNPACK2(c0, c1, A2); UNPACK2(d0, d1, A3);
        float s = ((a0 + a1) + (b0 + b1)) + ((c0 + c1) + (d0 + d1));
        float bs = block_reduce(s);
        if (threadIdx.x == 0) atomicAdd(&g_acc_bg, (double)bs);
        return;
    }

    // ---- per-box scatter ----
    __shared__ int   s_cxi, s_cyi, s_rw, s_idx0;
    __shared__ float s_sig2;
    int t = bid - BG_BLOCKS;               // box id = b*64 + n
    if (threadIdx.x == 0) {
        float x1 = boxes[4*t+0], y1 = boxes[4*t+1];
        float x2 = boxes[4*t+2], y2 = boxes[4*t+3];
        const float wr = 0.25f, hr = 0.25f;        // W/512, H/512
        float cx = ((x1 + x2) * wr) * 0.5f;
        float cy = ((y1 + y2) * hr) * 0.5f;
        int cxi = (int)floorf(cx);
        int cyi = (int)floorf(cy);
        float sw = (x2 - x1) * wr;
        float sh = (y2 - y1) * hr;

        // gaussian radius, reference fp32 op order
        float h = sh, w = sw;
        float b1 = h + w;
        float c1 = ((w * h) * 0.7f) / 1.3f;
        float sq1 = sqrtf(b1*b1 - 4.0f*c1);
        float r1 = (b1 - sq1) * 0.5f;
        float b2 = 2.0f * (h + w);
        float c2 = (0.7f * w) * h;
        float sq2 = sqrtf(b2*b2 - 16.0f*c2);
        float r2 = (b2 - sq2) * 0.125f;
        float b3 = -0.6f * (h + w);
        float c3 = (-0.7f * w) * h;
        float sq3 = sqrtf(b3*b3 - 4.8f*c3);
        float r3 = (b3 + sq3) / 2.4f;
        float rm = fminf(fminf(r1, r2), r3);
        int rad = (int)fmaxf(0.0f, floorf(rm));

        float d = (float)(2*rad + 1);
        float sig2 = ((2.0f * d) / 6.0f) * (d / 6.0f);
        int rw = rad < RMAX ? rad : RMAX;          // effective window radius

        int b = t >> 6, n = t & 63;
        int cls = labels[t];
        g_cxi[t] = cxi; g_cyi[t] = cyi; g_rw[t] = rw; g_cls[t] = cls;
        g_sig2[t] = sig2;
        g_fx[t] = cx - (float)cxi;  g_fy[t] = cy - (float)cyi;
        g_sw[t] = sw;               g_sh[t] = sh;

        // last-wins winner: max n == last sequential writer
        atomicMax(&g_win[b * HW + cyi * Ww + cxi], n + 1);

        s_cxi = cxi; s_cyi = cyi; s_rw = rw; s_sig2 = sig2;
        s_idx0 = ((b * Cc + cls) * Hh) * Ww;
    }
    __syncthreads();
    int rw = s_rw, wdim = 2*rw + 1, nwin = wdim * wdim;
    int cxi = s_cxi, cyi = s_cyi, idx0 = s_idx0;
    float inv_s2 = 1.0f / s_sig2;
    for (int i = threadIdx.x; i < nwin; i += blockDim.x) {
        int dy = i / wdim - rw;
        int dx = i - (dy + rw) * wdim - rw;
        int y = cyi + dy, x = cxi + dx;
        if ((unsigned)y < (unsigned)Hh && (unsigned)x < (unsigned)Ww) {
            float d2   = (float)(dx*dx + dy*dy);
            float kern = expf(-d2 * inv_s2);
            if (kern >= EPS32) {
                atomicMax((int*)&g_ct[idx0 + y * Ww + x], __float_as_int(kern));
            }
        }
    }
}

// ---------------------------------------------------------------------------
// Phase 2: one 256-thread block per box (row-contiguous window walk).
// atomicExch dedups overlapping windows AND re-zeroes g_ct for the next
// replay. Thread 0 handles wh/offset L1 at winner centers. Last block
// finalizes the loss and rezeros the scalar accumulators.
__global__ void __launch_bounds__(256) k_phase2(const float* __restrict__ cp,
                                                const float* __restrict__ wh,
                                                const float* __restrict__ off,
                                                float* __restrict__ out) {
    int t = blockIdx.x;                      // box id
    int rw  = g_rw[t], wdim = 2*rw + 1, nwin = wdim * wdim;
    int cxi = g_cxi[t], cyi = g_cyi[t];
    int b = t >> 6;
    int idx0 = ((b * Cc + g_cls[t]) * Hh) * Ww;

    float delta = 0.0f;
    int hits1 = 0;
    for (int i = threadIdx.x; i < nwin; i += blockDim.x) {
        int dy = i / wdim - rw;
        int dx = i - (dy + rw) * wdim - rw;
        int y = cyi + dy, x = cxi + dx;
        if ((unsigned)y < (unsigned)Hh && (unsigned)x < (unsigned)Ww) {
            int idx = idx0 + y * Ww + x;
            int old = atomicExch((int*)&g_ct[idx], 0);
            if (old != 0) {
                float v  = __int_as_float(old);
                float pv = cp[idx];
                float fb = f_bg_precise(pv);
                float om = 1.0f - v;
                float om2 = om * om;
                delta += fb * (om2 * om2 - 1.0f);
                if (v == 1.0f) {
                    float q = 1.0f - pv;
                    delta += -__logf(pv + 1e-12f) * (q * q);
                    hits1++;
                }
            }
        }
    }

    float bs = block_reduce(delta);
    __shared__ int sh_h[32];
    {   // block-reduce hits1
        int lane = threadIdx.x & 31, wid = threadIdx.x >> 5;
        #pragma unroll
        for (int o = 16; o > 0; o >>= 1) hits1 += __shfl_down_sync(0xffffffffu, hits1, o);
        if (lane == 0) sh_h[wid] = hits1;
        __syncthreads();
        hits1 = (threadIdx.x < 8) ? sh_h[threadIdx.x] : 0;
        if (wid == 0) {
            #pragma unroll
            for (int o = 4; o > 0; o >>= 1) hits1 += __shfl_down_sync(0xffffffffu, hits1, o);
        }
    }

    if (threadIdx.x == 0) {
        if (bs != 0.0f) atomicAdd(&g_acc_c, (double)bs);
        if (hits1)      atomicAdd(&g_af, hits1);
        // wh / offset at winner centers (CAS dedup + cleanup)
        int n = t & 63;
        int pix = cyi * Ww + cxi;
        if (atomicCAS(&g_win[b * HW + pix], n + 1, 0) == n + 1) {
            const float* wp = wh  + (size_t)b * 2 * HW;
            const float* op = off + (size_t)b * 2 * HW;
            float cw = fabsf(wp[pix] - g_sw[t]) + fabsf(wp[HW + pix] - g_sh[t]);
            float co = fabsf(op[pix] - g_fx[t]) + fabsf(op[HW + pix] - g_fy[t]);
            atomicAdd(&g_acc_wh, (double)cw);
            atomicAdd(&g_acc_of, (double)co);
        }
        __threadfence();
        int done = atomicAdd(&g_done, 1);
        if (done == gridDim.x - 1) {
            double accc  = atomicAdd(&g_acc_c, 0.0);
            double accbg = atomicAdd(&g_acc_bg, 0.0);
            double accwh = atomicAdd(&g_acc_wh, 0.0);
            double accof = atomicAdd(&g_acc_of, 0.0);
            int afi      = atomicAdd(&g_af, 0);
            float af = fmaxf(1.0f, (float)afi);
            double bg = -0.693147180559945309 * accbg;   // -ln2 * lg2-sum
            float lc = (float)(bg + accc) / (af + EPS32);
            float lw = (0.1f * (float)accwh) / (af * 2.0f + EPS32);
            float lo = (float)accof / (af * 2.0f + EPS32);
            out[0] = lc + lw + lo;
            // restore zero invariant for next graph replay
            g_acc_bg = 0.0; g_acc_c = 0.0; g_acc_wh = 0.0; g_acc_of = 0.0;
            g_af = 0; g_done = 0;
            __threadfence();
        }
    }
}

// ---------------------------------------------------------------------------
extern "C" void kernel_launch(void* const* d_in, const int* in_sizes, int n_in,
                              void* d_out, int out_size) {
    const float* cp     = (const float*)d_in[0];   // center_pred (16,80,128,128)
    const float* wh     = (const float*)d_in[1];   // wh_pred     (16,2,128,128)
    const float* off    = (const float*)d_in[2];   // offset_pred (16,2,128,128)
    const float* boxes  = (const float*)d_in[3];   // (16,64,4)
    const int*   labels = (const int*)d_in[4];     // (16,64)
    float* out = (float*)d_out;

    k_phase1<<<BG_BLOCKS + NB, 256>>>((const float4*)cp, boxes, labels);
    k_phase2<<<NB, 256>>>(cp, wh, off, out);
}

// round 13
// speedup vs baseline: 1.2199x; 1.2199x over previous
#include <cuda_runtime.h>
#include <math.h>

#define Bb 16
#define Nn 64
#define Cc 80
#define Hh 128
#define Ww 128
#define HW (Hh*Ww)
#define NB (Bb*Nn)
#define RMAX 16
#define EPS32 1.1920929e-07f
#define TOTAL (Bb*Cc*HW)

#define BG_BLOCKS 2560
#define N4 (TOTAL/4)              // 5,242,880 float4
#define BLK4 (N4/BG_BLOCKS)       // 2048 float4 per bg block = 8 * 256

// Persistent scratch. Invariants between launches (restored every launch):
//   g_ct, g_win all zero; g_acc_*, g_af, g_done zero.
// Zero at module load; phase2 restores g_ct via atomicExch, g_win via CAS,
// and the finalize block rezeros the scalar accumulators.
__device__ int   g_cxi[NB], g_cyi[NB], g_rw[NB], g_cls[NB];
__device__ float g_sig2[NB], g_fx[NB], g_fy[NB], g_sw[NB], g_sh[NB];
__device__ int   g_win[Bb*HW];
__device__ float g_ct[TOTAL];
__device__ double g_acc_bg;      // sum of lg2(1-p)*p^2 (scale by -ln2 at end)
__device__ double g_acc_c;       // focal corrections at ct>0 pixels
__device__ double g_acc_wh, g_acc_of;
__device__ int   g_af;
__device__ int   g_done;

// ---------------------------------------------------------------------------
__device__ __forceinline__ float block_reduce(float v) {
    __shared__ float sh[32];
    int lane = threadIdx.x & 31;
    int wid  = threadIdx.x >> 5;
    #pragma unroll
    for (int o = 16; o > 0; o >>= 1) v += __shfl_down_sync(0xffffffffu, v, o);
    if (lane == 0) sh[wid] = v;
    __syncthreads();
    int nw = (blockDim.x + 31) >> 5;
    v = (threadIdx.x < nw) ? sh[threadIdx.x] : 0.0f;
    if (wid == 0) {
        #pragma unroll
        for (int o = 16; o > 0; o >>= 1) v += __shfl_down_sync(0xffffffffu, v, o);
    }
    return v;  // valid on thread 0
}

__device__ __forceinline__ float f_bg_precise(float p) {
    return -__logf(1.0f - p + 1e-12f) * (p * p);
}

// packed f32x2 helpers
#define PACK2(out, lo, hi) asm("mov.b64 %0, {%1, %2};" : "=l"(out) : "f"(lo), "f"(hi))
#define UNPACK2(lo, hi, in) asm("mov.b64 {%0, %1}, %2;" : "=f"(lo), "=f"(hi) : "l"(in))
#define FMA2(out, a, b, c) asm("fma.rn.f32x2 %0, %1, %2, %3;" : "=l"(out) : "l"(a), "l"(b), "l"(c))
#define MUL2(out, a, b)    asm("mul.rn.f32x2 %0, %1, %2;" : "=l"(out) : "l"(a), "l"(b))
#define LG2(out, in)       asm("lg2.approx.f32 %0, %1;" : "=f"(out) : "f"(in))

// acc += lg2(1-p) * p^2   (elementwise on a packed pair)
__device__ __forceinline__ void bg_pair(unsigned long long P,
                                        unsigned long long NEG2,
                                        unsigned long long ONE2,
                                        unsigned long long& ACC) {
    unsigned long long T, Q, L;
    FMA2(T, P, NEG2, ONE2);         // t = 1 - p
    float t0, t1, l0, l1;
    UNPACK2(t0, t1, T);
    LG2(l0, t0);
    LG2(l1, t1);
    PACK2(L, l0, l1);
    MUL2(Q, P, P);                  // p^2
    FMA2(ACC, L, Q, ACC);           // acc += lg2(t) * p^2
}

__device__ __forceinline__ void bg_quad(float4 v,
                                        unsigned long long NEG2,
                                        unsigned long long ONE2,
                                        unsigned long long& A0,
                                        unsigned long long& A1) {
    unsigned long long P;
    PACK2(P, v.x, v.y); bg_pair(P, NEG2, ONE2, A0);
    PACK2(P, v.z, v.w); bg_pair(P, NEG2, ONE2, A1);
}

// ---------------------------------------------------------------------------
// Phase 1 (byte-identical to the 19.9us best): 
//   blocks [0, BG_BLOCKS)   -> dense background lg2-sum over 84 MB
//                              (batched loads: 4 float4 in flight)
//   blocks [BG_BLOCKS,+NB)  -> per-box params + winner map + gaussian
//                              scatter-max (fills the bg drain)
__global__ void __launch_bounds__(256) k_phase1(const float4* __restrict__ cp4,
                                                const float*  __restrict__ boxes,
                                                const int*    __restrict__ labels) {
    int bid = blockIdx.x;
    if (bid < BG_BLOCKS) {
        // ---- dense background term ----
        const float4* p = cp4 + bid * BLK4 + threadIdx.x;
        unsigned long long ONE2, NEG2, A0 = 0, A1 = 0, A2 = 0, A3 = 0;
        PACK2(ONE2, 1.0f, 1.0f);
        PACK2(NEG2, -1.0f, -1.0f);
        #pragma unroll
        for (int r = 0; r < 2; r++) {           // BLK4 = 8 * 256, exact
            float4 v0 = p[r*1024 +   0];
            float4 v1 = p[r*1024 + 256];
            float4 v2 = p[r*1024 + 512];
            float4 v3 = p[r*1024 + 768];
            bg_quad(v0, NEG2, ONE2, A0, A1);
            bg_quad(v1, NEG2, ONE2, A2, A3);
            bg_quad(v2, NEG2, ONE2, A0, A1);
            bg_quad(v3, NEG2, ONE2, A2, A3);
        }
        float a0, a1, b0, b1, c0, c1, d0, d1;
        UNPACK2(a0, a1, A0); UNPACK2(b0, b1, A1);
        UNPACK2(c0, c1, A2); UNPACK2(d0, d1, A3);
        float s = ((a0 + a1) + (b0 + b1)) + ((c0 + c1) + (d0 + d1));
        float bs = block_reduce(s);
        if (threadIdx.x == 0) atomicAdd(&g_acc_bg, (double)bs);
        return;
    }

    // ---- per-box scatter ----
    __shared__ int   s_cxi, s_cyi, s_rw, s_idx0;
    __shared__ float s_sig2;
    int t = bid - BG_BLOCKS;               // box id = b*64 + n
    if (threadIdx.x == 0) {
        float x1 = boxes[4*t+0], y1 = boxes[4*t+1];
        float x2 = boxes[4*t+2], y2 = boxes[4*t+3];
        const float wr = 0.25f, hr = 0.25f;        // W/512, H/512
        float cx = ((x1 + x2) * wr) * 0.5f;
        float cy = ((y1 + y2) * hr) * 0.5f;
        int cxi = (int)floorf(cx);
        int cyi = (int)floorf(cy);
        float sw = (x2 - x1) * wr;
        float sh = (y2 - y1) * hr;

        // gaussian radius, reference fp32 op order
        float h = sh, w = sw;
        float b1 = h + w;
        float c1 = ((w * h) * 0.7f) / 1.3f;
        float sq1 = sqrtf(b1*b1 - 4.0f*c1);
        float r1 = (b1 - sq1) * 0.5f;
        float b2 = 2.0f * (h + w);
        float c2 = (0.7f * w) * h;
        float sq2 = sqrtf(b2*b2 - 16.0f*c2);
        float r2 = (b2 - sq2) * 0.125f;
        float b3 = -0.6f * (h + w);
        float c3 = (-0.7f * w) * h;
        float sq3 = sqrtf(b3*b3 - 4.8f*c3);
        float r3 = (b3 + sq3) / 2.4f;
        float rm = fminf(fminf(r1, r2), r3);
        int rad = (int)fmaxf(0.0f, floorf(rm));

        float d = (float)(2*rad + 1);
        float sig2 = ((2.0f * d) / 6.0f) * (d / 6.0f);
        int rw = rad < RMAX ? rad : RMAX;          // effective window radius

        int b = t >> 6, n = t & 63;
        int cls = labels[t];
        g_cxi[t] = cxi; g_cyi[t] = cyi; g_rw[t] = rw; g_cls[t] = cls;
        g_sig2[t] = sig2;
        g_fx[t] = cx - (float)cxi;  g_fy[t] = cy - (float)cyi;
        g_sw[t] = sw;               g_sh[t] = sh;

        // last-wins winner: max n == last sequential writer
        atomicMax(&g_win[b * HW + cyi * Ww + cxi], n + 1);

        s_cxi = cxi; s_cyi = cyi; s_rw = rw; s_sig2 = sig2;
        s_idx0 = ((b * Cc + cls) * Hh) * Ww;
    }
    __syncthreads();
    int rw = s_rw, wdim = 2*rw + 1, nwin = wdim * wdim;
    int cxi = s_cxi, cyi = s_cyi, idx0 = s_idx0;
    float inv_s2 = 1.0f / s_sig2;
    for (int i = threadIdx.x; i < nwin; i += blockDim.x) {
        int dy = i / wdim - rw;
        int dx = i - (dy + rw) * wdim - rw;
        int y = cyi + dy, x = cxi + dx;
        if ((unsigned)y < (unsigned)Hh && (unsigned)x < (unsigned)Ww) {
            float d2   = (float)(dx*dx + dy*dy);
            float kern = expf(-d2 * inv_s2);
            if (kern >= EPS32) {
                atomicMax((int*)&g_ct[idx0 + y * Ww + x], __float_as_int(kern));
            }
        }
    }
}

// ---------------------------------------------------------------------------
// Phase 2: one 256-thread block per box, 2-way unrolled window walk: both
// atomicExch's and both cp loads are issued before either result is
// consumed, doubling atomic/load MLP. atomicExch dedups overlapping
// windows AND re-zeroes g_ct. Thread 0 handles wh/offset L1; last block
// finalizes and rezeros the scalar accumulators.
__global__ void __launch_bounds__(256) k_phase2(const float* __restrict__ cp,
                                                const float* __restrict__ wh,
                                                const float* __restrict__ off,
                                                float* __restrict__ out) {
    int t = blockIdx.x;                      // box id
    int rw  = g_rw[t], wdim = 2*rw + 1, nwin = wdim * wdim;
    int cxi = g_cxi[t], cyi = g_cyi[t];
    int b = t >> 6;
    int idx0 = ((b * Cc + g_cls[t]) * Hh) * Ww;

    float delta = 0.0f;
    int hits1 = 0;
    for (int base = 0; base < nwin; base += 512) {
        int i0 = base + threadIdx.x;
        int i1 = i0 + 256;
        // compute both indices (or -1 if out of window/image)
        int idxA = -1, idxB = -1;
        if (i0 < nwin) {
            int dy = i0 / wdim - rw;
            int dx = i0 - (dy + rw) * wdim - rw;
            int y = cyi + dy, x = cxi + dx;
            if ((unsigned)y < (unsigned)Hh && (unsigned)x < (unsigned)Ww)
                idxA = idx0 + y * Ww + x;
        }
        if (i1 < nwin) {
            int dy = i1 / wdim - rw;
            int dx = i1 - (dy + rw) * wdim - rw;
            int y = cyi + dy, x = cxi + dx;
            if ((unsigned)y < (unsigned)Hh && (unsigned)x < (unsigned)Ww)
                idxB = idx0 + y * Ww + x;
        }
        // issue both exchanges + both prediction loads back-to-back
        int oldA = 0, oldB = 0;
        float pvA = 0.0f, pvB = 0.0f;
        if (idxA >= 0) { pvA = cp[idxA]; oldA = atomicExch((int*)&g_ct[idxA], 0); }
        if (idxB >= 0) { pvB = cp[idxB]; oldB = atomicExch((int*)&g_ct[idxB], 0); }
        // consume
        if (oldA != 0) {
            float v  = __int_as_float(oldA);
            float fb = f_bg_precise(pvA);
            float om = 1.0f - v;
            float om2 = om * om;
            delta += fb * (om2 * om2 - 1.0f);
            if (v == 1.0f) {
                float q = 1.0f - pvA;
                delta += -__logf(pvA + 1e-12f) * (q * q);
                hits1++;
            }
        }
        if (oldB != 0) {
            float v  = __int_as_float(oldB);
            float fb = f_bg_precise(pvB);
            float om = 1.0f - v;
            float om2 = om * om;
            delta += fb * (om2 * om2 - 1.0f);
            if (v == 1.0f) {
                float q = 1.0f - pvB;
                delta += -__logf(pvB + 1e-12f) * (q * q);
                hits1++;
            }
        }
    }

    float bs = block_reduce(delta);
    __shared__ int sh_h[32];
    {   // block-reduce hits1
        int lane = threadIdx.x & 31, wid = threadIdx.x >> 5;
        #pragma unroll
        for (int o = 16; o > 0; o >>= 1) hits1 += __shfl_down_sync(0xffffffffu, hits1, o);
        if (lane == 0) sh_h[wid] = hits1;
        __syncthreads();
        hits1 = (threadIdx.x < 8) ? sh_h[threadIdx.x] : 0;
        if (wid == 0) {
            #pragma unroll
            for (int o = 4; o > 0; o >>= 1) hits1 += __shfl_down_sync(0xffffffffu, hits1, o);
        }
    }

    if (threadIdx.x == 0) {
        if (bs != 0.0f) atomicAdd(&g_acc_c, (double)bs);
        if (hits1)      atomicAdd(&g_af, hits1);
        // wh / offset at winner centers (CAS dedup + cleanup)
        int n = t & 63;
        int pix = cyi * Ww + cxi;
        if (atomicCAS(&g_win[b * HW + pix], n + 1, 0) == n + 1) {
            const float* wp = wh  + (size_t)b * 2 * HW;
            const float* op = off + (size_t)b * 2 * HW;
            float cw = fabsf(wp[pix] - g_sw[t]) + fabsf(wp[HW + pix] - g_sh[t]);
            float co = fabsf(op[pix] - g_fx[t]) + fabsf(op[HW + pix] - g_fy[t]);
            atomicAdd(&g_acc_wh, (double)cw);
            atomicAdd(&g_acc_of, (double)co);
        }
        __threadfence();
        int done = atomicAdd(&g_done, 1);
        if (done == gridDim.x - 1) {
            double accc  = atomicAdd(&g_acc_c, 0.0);
            double accbg = atomicAdd(&g_acc_bg, 0.0);
            double accwh = atomicAdd(&g_acc_wh, 0.0);
            double accof = atomicAdd(&g_acc_of, 0.0);
            int afi      = atomicAdd(&g_af, 0);
            float af = fmaxf(1.0f, (float)afi);
            double bg = -0.693147180559945309 * accbg;   // -ln2 * lg2-sum
            float lc = (float)(bg + accc) / (af + EPS32);
            float lw = (0.1f * (float)accwh) / (af * 2.0f + EPS32);
            float lo = (float)accof / (af * 2.0f + EPS32);
            out[0] = lc + lw + lo;
            // restore zero invariant for next graph replay
            g_acc_bg = 0.0; g_acc_c = 0.0; g_acc_wh = 0.0; g_acc_of = 0.0;
            g_af = 0; g_done = 0;
            __threadfence();
        }
    }
}

// ---------------------------------------------------------------------------
extern "C" void kernel_launch(void* const* d_in, const int* in_sizes, int n_in,
                              void* d_out, int out_size) {
    const float* cp     = (const float*)d_in[0];   // center_pred (16,80,128,128)
    const float* wh     = (const float*)d_in[1];   // wh_pred     (16,2,128,128)
    const float* off    = (const float*)d_in[2];   // offset_pred (16,2,128,128)
    const float* boxes  = (const float*)d_in[3];   // (16,64,4)
    const int*   labels = (const int*)d_in[4];     // (16,64)
    float* out = (float*)d_out;

    k_phase1<<<BG_BLOCKS + NB, 256>>>((const float4*)cp, boxes, labels);
    k_phase2<<<NB, 256>>>(cp, wh, off, out);
}